// round 17
// baseline (speedup 1.0000x reference)
#include <cuda_runtime.h>
#include <cuda.h>
#include <cuda_fp16.h>
#include <cuda_bf16.h>
#include <cstdint>

#define M_DIM 16384
#define N_DIM 2048
#define K_DIM 2048

// ---- tcgen05 availability: only on arch-specific/family sm_100+ passes ----
#if defined(__CUDA_ARCH__) && (defined(__CUDA_ARCH_FEAT_SM103_ALL) ||          \
    defined(__CUDA_ARCH_FEAT_SM100_ALL) ||                                     \
    (defined(__CUDA_ARCH_FAMILY_SPECIFIC__) && (__CUDA_ARCH_FAMILY_SPECIFIC__ >= 1000)))
#define HAVE_TC 1
#else
#define HAVE_TC 0
#endif

// ---- allocation-free device scratch ---------------------------------------
__device__ __align__(256) __nv_bfloat16 g_xbf[(size_t)M_DIM * K_DIM];   // 64 MB
__device__ __align__(256) __nv_bfloat16 g_wTbf[(size_t)N_DIM * K_DIM]; //  8 MB [N][K]
__device__ int g_x_wide;
__device__ int g_w_wide;

// ---------------------------------------------------------------------------
// Detect int32-widened inputs (high byte of each 4B group is 0x00/0xFF).
// ---------------------------------------------------------------------------
__global__ void detect_kernel(const uint8_t* __restrict__ x,
                              const uint8_t* __restrict__ w) {
    __shared__ int sx, sw;
    if (threadIdx.x == 0) { sx = 1; sw = 1; }
    __syncthreads();
    int okx = 1, okw = 1;
    for (int i = threadIdx.x; i < 1024; i += 256) {
        uint8_t bx = x[4 * i + 3];
        uint8_t bw = w[4 * i + 3];
        if (bx != 0x00 && bx != 0xFF) okx = 0;
        if (bw != 0x00 && bw != 0xFF) okw = 0;
    }
    if (!okx) atomicAnd(&sx, 0);
    if (!okw) atomicAnd(&sw, 0);
    __syncthreads();
    if (threadIdx.x == 0) { g_x_wide = sx; g_w_wide = sw; }
}

// ---------------------------------------------------------------------------
// x -> bf16.  16 elements/thread.
// ---------------------------------------------------------------------------
__global__ void pack_x_bf16_kernel(const void* __restrict__ xin) {
    const size_t e0 = ((size_t)blockIdx.x * blockDim.x + threadIdx.x) * 16;
    if (e0 >= (size_t)M_DIM * K_DIM) return;
    __nv_bfloat16 tmp[16];
    if (g_x_wide) {
        const int4* p = (const int4*)xin + e0 / 4;
#pragma unroll
        for (int j = 0; j < 4; j++) {
            int4 v = p[j];
            tmp[4 * j + 0] = __int2bfloat16_rn(v.x);
            tmp[4 * j + 1] = __int2bfloat16_rn(v.y);
            tmp[4 * j + 2] = __int2bfloat16_rn(v.z);
            tmp[4 * j + 3] = __int2bfloat16_rn(v.w);
        }
    } else {
        const int8_t* p = (const int8_t*)xin + e0;
        int8_t b[16];
        *(int4*)b = *(const int4*)p;
#pragma unroll
        for (int j = 0; j < 16; j++) tmp[j] = __int2bfloat16_rn((int)b[j]);
    }
    *(uint4*)&g_xbf[e0]     = *(const uint4*)tmp;
    *(uint4*)&g_xbf[e0 + 8] = *(const uint4*)(tmp + 8);
}

// ---------------------------------------------------------------------------
// weight [K][N] -> g_wTbf [N][K] bf16.
// ---------------------------------------------------------------------------
__global__ void pack_w_bf16T_kernel(const void* __restrict__ w) {
    __shared__ __nv_bfloat16 tile[32][33];
    const int n0 = blockIdx.x * 32;
    const int k0 = blockIdx.y * 32;
    const int tx = threadIdx.x;
    const int ty = threadIdx.y;
    if (g_w_wide) {
        const int* w32 = (const int*)w;
#pragma unroll
        for (int j = 0; j < 32; j += 8)
            tile[ty + j][tx] = __int2bfloat16_rn(w32[(size_t)(k0 + ty + j) * N_DIM + (n0 + tx)]);
    } else {
        const int8_t* w8 = (const int8_t*)w;
#pragma unroll
        for (int j = 0; j < 32; j += 8)
            tile[ty + j][tx] = __int2bfloat16_rn((int)w8[(size_t)(k0 + ty + j) * N_DIM + (n0 + tx)]);
    }
    __syncthreads();
#pragma unroll
    for (int j = 0; j < 32; j += 8)
        g_wTbf[(size_t)(n0 + ty + j) * K_DIM + (k0 + tx)] = tile[tx][ty + j];
}

// ---------------------------------------------------------------------------
__device__ __forceinline__ uint32_t cvta_smem(const void* p) {
    return (uint32_t)__cvta_generic_to_shared(p);
}

// ===========================================================================
// shared tc constants
// ===========================================================================
#define TBM 256
#define TBN 256
#define TBKE 64
#define KCHUNKS (K_DIM / TBKE)           // 32
#define NSTAGE 3

#define SWZ(o) ((o) ^ (((o) >> 3) & 0x70))

#define SM_TMEM 0
#define SM_MBAR 64                            // full[3] @64, done[3] @88
#define SM_A    1024                          // 3 stages x 32 KB
#define SM_B    (1024 + NSTAGE * 32768)
#define SMEM_TOTAL (1024 + NSTAGE * 2 * 32768)   // 197632 B

#if HAVE_TC
__device__ __forceinline__ void mbar_init(uint32_t a, uint32_t cnt) {
    asm volatile("mbarrier.init.shared.b64 [%0], %1;" :: "r"(a), "r"(cnt) : "memory");
}
__device__ __forceinline__ void mbar_wait(uint32_t a, uint32_t parity) {
    asm volatile(
        "{\n\t"
        ".reg .pred P1;\n\t"
        "WAIT_LOOP_%=:\n\t"
        "mbarrier.try_wait.parity.shared.b64 P1, [%0], %1;\n\t"
        "@P1 bra.uni WAIT_DONE_%=;\n\t"
        "bra.uni WAIT_LOOP_%=;\n\t"
        "WAIT_DONE_%=:\n\t"
        "}"
        :: "r"(a), "r"(parity) : "memory");
}
__device__ __forceinline__ void mbar_expect_tx(uint32_t a, uint32_t bytes) {
    asm volatile("mbarrier.arrive.expect_tx.shared.b64 _, [%0], %1;"
                 :: "r"(a), "r"(bytes) : "memory");
}
__device__ __forceinline__ void tma_load_2d(uint32_t dst, const CUtensorMap* map,
                                            int x, int y, uint32_t mbar) {
    asm volatile(
        "cp.async.bulk.tensor.2d.shared::cta.global.tile.mbarrier::complete_tx::bytes "
        "[%0], [%1, {%2, %3}], [%4];"
        :: "r"(dst), "l"(map), "r"(x), "r"(y), "r"(mbar) : "memory");
}
static __device__ __forceinline__ uint64_t make_desc_sw128(uint32_t addr) {
    return ((uint64_t)2 << 61) | ((uint64_t)1 << 46) | ((uint64_t)64 << 32) |
           ((uint64_t)1 << 16) | (((uint64_t)addr >> 4) & 0x3FFF);
}
// idesc kind::f16 (bf16 in, fp32 acc): dtype F32@4, a/b BF16@[7]/[10],
// N/8@[17:22]=16 (N=128), M/16@[24:28]=8 (M=128)
#define IDESC_BF16 ((1u << 4) | (1u << 7) | (1u << 10) | (16u << 17) | (8u << 24))

__device__ __forceinline__ void mma_bf16_ss(uint32_t d_tmem, uint64_t a_desc,
                                            uint64_t b_desc, uint32_t en) {
    asm volatile(
        "{\n\t"
        ".reg .pred p;\n\t"
        "setp.ne.u32 p, %5, 0;\n\t"
        "tcgen05.mma.cta_group::1.kind::f16 [%0], %1, %2, %3, {%4,%4,%4,%4}, p;\n\t"
        "}"
        :: "r"(d_tmem), "l"(a_desc), "l"(b_desc), "r"(IDESC_BF16), "r"(0u), "r"(en)
        : "memory");
}
__device__ __forceinline__ void mma_commit(uint32_t mbar) {
    asm volatile(
        "tcgen05.commit.cta_group::1.mbarrier::arrive::one.shared::cluster.b64 [%0];"
        :: "r"(mbar) : "memory");
}

// shared epilogue: TMEM -> registers -> out (+bias)
__device__ __forceinline__ void tc_epilogue(uint32_t tmem, int bm, int bn,
                                            const __half* bias, float* out,
                                            int wid, int lane) {
    const int slab = wid >> 2;
    const int sp   = wid & 3;
    const size_t m = (size_t)(bm * TBM + slab * 128 + sp * 32 + lane);
    const uint32_t dbase = tmem + slab * 256;
#pragma unroll
    for (int cb = 0; cb < 256; cb += 32) {
        uint32_t r[32];
        asm volatile(
            "tcgen05.ld.sync.aligned.32x32b.x32.b32 "
            "{%0,%1,%2,%3,%4,%5,%6,%7,%8,%9,%10,%11,%12,%13,%14,%15,"
            "%16,%17,%18,%19,%20,%21,%22,%23,%24,%25,%26,%27,%28,%29,%30,%31}, [%32];"
            : "=r"(r[0]), "=r"(r[1]), "=r"(r[2]), "=r"(r[3]),
              "=r"(r[4]), "=r"(r[5]), "=r"(r[6]), "=r"(r[7]),
              "=r"(r[8]), "=r"(r[9]), "=r"(r[10]), "=r"(r[11]),
              "=r"(r[12]), "=r"(r[13]), "=r"(r[14]), "=r"(r[15]),
              "=r"(r[16]), "=r"(r[17]), "=r"(r[18]), "=r"(r[19]),
              "=r"(r[20]), "=r"(r[21]), "=r"(r[22]), "=r"(r[23]),
              "=r"(r[24]), "=r"(r[25]), "=r"(r[26]), "=r"(r[27]),
              "=r"(r[28]), "=r"(r[29]), "=r"(r[30]), "=r"(r[31])
            : "r"(dbase + cb));
        asm volatile("tcgen05.wait::ld.sync.aligned;" ::: "memory");

        const int n0 = bn * TBN + cb;
        float* op = out + m * N_DIM + n0;
#pragma unroll
        for (int j = 0; j < 32; j += 4) {
            float4 v;
            v.x = __uint_as_float(r[j + 0]) + __half2float(bias[n0 + j + 0]);
            v.y = __uint_as_float(r[j + 1]) + __half2float(bias[n0 + j + 1]);
            v.z = __uint_as_float(r[j + 2]) + __half2float(bias[n0 + j + 2]);
            v.w = __uint_as_float(r[j + 3]) + __half2float(bias[n0 + j + 3]);
            *(float4*)&op[j] = v;
        }
    }
}
#endif  // HAVE_TC

// ===========================================================================
// TMA-driven tcgen05 GEMM: single driver thread issues TMA + MMA; other
// threads park until epilogue.  2 loads/chunk instead of 4096 cp.async.
// ===========================================================================
__global__ __launch_bounds__(256, 1)
void tc_gemm_tma(const __grid_constant__ CUtensorMap mapA,
                 const __grid_constant__ CUtensorMap mapB,
                 const __half* __restrict__ bias, float* __restrict__ out) {
#if HAVE_TC
    extern __shared__ __align__(1024) char smem[];
    const uint32_t smem_base = cvta_smem(smem);
    const int tid  = threadIdx.x;
    const int lane = tid & 31;
    const int wid  = tid >> 5;
    const int bn   = blockIdx.x;     // 0..7
    const int bm   = blockIdx.y;     // 0..63

    if (wid == 0) {
        asm volatile("tcgen05.alloc.cta_group::1.sync.aligned.shared::cta.b32 [%0], %1;"
                     :: "r"(smem_base + SM_TMEM), "r"(512u) : "memory");
        asm volatile("tcgen05.relinquish_alloc_permit.cta_group::1.sync.aligned;");
    }
    if (tid == 0) {
#pragma unroll
        for (int s = 0; s < NSTAGE; s++) {
            mbar_init(smem_base + SM_MBAR + s * 8, 1);        // full[s]
            mbar_init(smem_base + SM_MBAR + 24 + s * 8, 1);   // done[s]
        }
    }
    __syncthreads();

    uint32_t tmem;
    asm volatile("ld.shared.b32 %0, [%1];" : "=r"(tmem) : "r"(smem_base + SM_TMEM));

    if (tid == 0) {
        int fph[NSTAGE] = {0, 0, 0};
        int dph[NSTAGE] = {0, 0, 0};

        auto issue_load = [&](int c) {
            const int s = c % NSTAGE;
            const uint32_t full = smem_base + SM_MBAR + s * 8;
            mbar_expect_tx(full, 65536);
            tma_load_2d(smem_base + SM_A + s * 32768, &mapA,
                        c * TBKE, bm * TBM, full);
            tma_load_2d(smem_base + SM_B + s * 32768, &mapB,
                        c * TBKE, bn * TBN, full);
        };
        auto wait_done = [&](int s) {
            mbar_wait(smem_base + SM_MBAR + 24 + s * 8, dph[s] & 1);
            dph[s]++;
        };

        issue_load(0);
        issue_load(1);

        for (int c = 0; c < KCHUNKS; c++) {
            const int s = c % NSTAGE;
            if (c + 2 < KCHUNKS) {
                const int s2 = (c + 2) % NSTAGE;
                if (c >= 1) wait_done(s2);           // chunk c-1's MMA on s2
                issue_load(c + 2);
            }
            mbar_wait(smem_base + SM_MBAR + s * 8, fph[s] & 1);   // TMA full
            fph[s]++;

            const uint64_t ad = make_desc_sw128(smem_base + SM_A + s * 32768);
            const uint64_t bd = make_desc_sw128(smem_base + SM_B + s * 32768);
#pragma unroll
            for (int k = 0; k < 4; k++) {            // k16 steps: +2 desc units
                const uint32_t en = (c > 0 || k > 0) ? 1u : 0u;
#pragma unroll
                for (int sl = 0; sl < 2; sl++) {     // M slabs: +1024 units
                    const uint64_t a = ad + sl * 1024 + k * 2;
                    mma_bf16_ss(tmem + sl * 256,       a, bd + k * 2,        en);
                    mma_bf16_ss(tmem + sl * 256 + 128, a, bd + 1024 + k * 2, en);
                }
            }
            mma_commit(smem_base + SM_MBAR + 24 + s * 8);
        }

        // drain: chunks 29,30,31 (per-stage completions, waited in order)
        wait_done((KCHUNKS - 3) % NSTAGE);
        wait_done((KCHUNKS - 2) % NSTAGE);
        wait_done((KCHUNKS - 1) % NSTAGE);
    }

    __syncthreads();
    asm volatile("tcgen05.fence::after_thread_sync;" ::: "memory");

    tc_epilogue(tmem, bm, bn, bias, out, wid, lane);

    __syncthreads();
    if (wid == 0) {
        asm volatile("tcgen05.dealloc.cta_group::1.sync.aligned.b32 %0, %1;"
                     :: "r"(tmem), "r"(512u));
    }
#endif  // HAVE_TC
}

// ===========================================================================
// Fallback: proven R11 cp.async kernel (launched only if TMA setup fails).
// ===========================================================================
__global__ __launch_bounds__(256, 1)
void tc_gemm_ca(const __half* __restrict__ bias, float* __restrict__ out) {
#if HAVE_TC
    extern __shared__ __align__(1024) char smem[];
    const uint32_t smem_base = cvta_smem(smem);
    const int tid  = threadIdx.x;
    const int lane = tid & 31;
    const int wid  = tid >> 5;
    const int bn   = blockIdx.x;
    const int bm   = blockIdx.y;

    const __nv_bfloat16* gA = g_xbf  + (size_t)(bm * TBM) * K_DIM;
    const __nv_bfloat16* gB = g_wTbf + (size_t)(bn * TBN) * K_DIM;

    if (wid == 0) {
        asm volatile("tcgen05.alloc.cta_group::1.sync.aligned.shared::cta.b32 [%0], %1;"
                     :: "r"(smem_base + SM_TMEM), "r"(512u) : "memory");
        asm volatile("tcgen05.relinquish_alloc_permit.cta_group::1.sync.aligned;");
    }
    if (tid == 0) {
        mbar_init(smem_base + SM_MBAR, 1);
        mbar_init(smem_base + SM_MBAR + 8, 1);
    }
    __syncthreads();

    uint32_t tmem;
    asm volatile("ld.shared.b32 %0, [%1];" : "=r"(tmem) : "r"(smem_base + SM_TMEM));

    auto load_chunk = [&](int c) {
        const int st = c % NSTAGE;
        const int kk = c * TBKE;
        const uint32_t abase = smem_base + SM_A + st * 32768;
        const uint32_t bbase = smem_base + SM_B + st * 32768;
#pragma unroll
        for (int i = 0; i < 8; i++) {
            const int idx = tid + i * 256;
            const int row = idx >> 3;
            const int ce  = (idx & 7) * 8;
            const uint32_t dst = abase + SWZ(row * 128 + ce * 2);
            const __nv_bfloat16* src = gA + (size_t)row * K_DIM + kk + ce;
            asm volatile("cp.async.cg.shared.global [%0], [%1], 16;\n"
                         :: "r"(dst), "l"(src));
        }
#pragma unroll
        for (int i = 0; i < 8; i++) {
            const int idx = tid + i * 256;
            const int row = idx >> 3;
            const int ce  = (idx & 7) * 8;
            const uint32_t dst = bbase + SWZ(row * 128 + ce * 2);
            const __nv_bfloat16* src = gB + (size_t)row * K_DIM + kk + ce;
            asm volatile("cp.async.cg.shared.global [%0], [%1], 16;\n"
                         :: "r"(dst), "l"(src));
        }
        asm volatile("cp.async.commit_group;\n");
    };

    load_chunk(0);
    load_chunk(1);

    int ph[2] = {0, 0};
    auto wait_mma = [&](int c) {
        const int i = c & 1;
        mbar_wait(smem_base + SM_MBAR + i * 8, ph[i]);
        ph[i] ^= 1;
    };

    for (int c = 0; c < KCHUNKS; c++) {
        if (c < KCHUNKS - 1) asm volatile("cp.async.wait_group 1;\n");
        else                 asm volatile("cp.async.wait_group 0;\n");
        asm volatile("fence.proxy.async.shared::cta;" ::: "memory");
        __syncthreads();

        const int st = c % NSTAGE;
        if (tid == 0) {
            const uint64_t ad = make_desc_sw128(smem_base + SM_A + st * 32768);
            const uint64_t bd = make_desc_sw128(smem_base + SM_B + st * 32768);
#pragma unroll
            for (int k = 0; k < 4; k++) {
                const uint32_t en = (c > 0 || k > 0) ? 1u : 0u;
#pragma unroll
                for (int sl = 0; sl < 2; sl++) {
                    const uint64_t a = ad + sl * 1024 + k * 2;
                    mma_bf16_ss(tmem + sl * 256,       a, bd + k * 2,        en);
                    mma_bf16_ss(tmem + sl * 256 + 128, a, bd + 1024 + k * 2, en);
                }
            }
            mma_commit(smem_base + SM_MBAR + (c & 1) * 8);
        }

        if (c + 2 < KCHUNKS) {
            if (c >= 1) wait_mma(c - 1);
            load_chunk(c + 2);
        }
    }

    mbar_wait(smem_base + SM_MBAR,     ph[0]);
    mbar_wait(smem_base + SM_MBAR + 8, ph[1] ^ 1);
    asm volatile("tcgen05.fence::after_thread_sync;" ::: "memory");

    tc_epilogue(tmem, bm, bn, bias, out, wid, lane);

    __syncthreads();
    if (wid == 0) {
        asm volatile("tcgen05.dealloc.cta_group::1.sync.aligned.b32 %0, %1;"
                     :: "r"(tmem), "r"(512u));
    }
#endif  // HAVE_TC
}

// ---------------------------------------------------------------------------
// Host: build tensormaps once via driver entry point (no -lcuda needed).
// ---------------------------------------------------------------------------
typedef CUresult (*PFN_tmap_encode)(
    CUtensorMap*, CUtensorMapDataType, cuuint32_t, void*,
    const cuuint64_t*, const cuuint64_t*, const cuuint32_t*, const cuuint32_t*,
    CUtensorMapInterleave, CUtensorMapSwizzle, CUtensorMapL2promotion,
    CUtensorMapFloatOOBfill);

static CUtensorMap h_mapA, h_mapB;
static int g_tma_ok = -1;

static void setup_tma() {
    g_tma_ok = 0;
    PFN_tmap_encode fn = nullptr;
    cudaDriverEntryPointQueryResult qr;
    if (cudaGetDriverEntryPoint("cuTensorMapEncodeTiled", (void**)&fn,
                                cudaEnableDefault, &qr) != cudaSuccess || !fn)
        return;
    void *xa = nullptr, *wa = nullptr;
    if (cudaGetSymbolAddress(&xa, g_xbf) != cudaSuccess) return;
    if (cudaGetSymbolAddress(&wa, g_wTbf) != cudaSuccess) return;

    cuuint64_t dimsA[2]    = {(cuuint64_t)K_DIM, (cuuint64_t)M_DIM};
    cuuint64_t dimsB[2]    = {(cuuint64_t)K_DIM, (cuuint64_t)N_DIM};
    cuuint64_t strides[1]  = {(cuuint64_t)K_DIM * 2};
    cuuint32_t box[2]      = {TBKE, 256};          // 64 elems (128B) x 256 rows
    cuuint32_t estr[2]     = {1, 1};

    CUresult r1 = fn(&h_mapA, CU_TENSOR_MAP_DATA_TYPE_BFLOAT16, 2, xa,
                     dimsA, strides, box, estr,
                     CU_TENSOR_MAP_INTERLEAVE_NONE, CU_TENSOR_MAP_SWIZZLE_128B,
                     CU_TENSOR_MAP_L2_PROMOTION_L2_128B,
                     CU_TENSOR_MAP_FLOAT_OOB_FILL_NONE);
    CUresult r2 = fn(&h_mapB, CU_TENSOR_MAP_DATA_TYPE_BFLOAT16, 2, wa,
                     dimsB, strides, box, estr,
                     CU_TENSOR_MAP_INTERLEAVE_NONE, CU_TENSOR_MAP_SWIZZLE_128B,
                     CU_TENSOR_MAP_L2_PROMOTION_L2_128B,
                     CU_TENSOR_MAP_FLOAT_OOB_FILL_NONE);
    g_tma_ok = (r1 == CUDA_SUCCESS && r2 == CUDA_SUCCESS);
}

extern "C" void kernel_launch(void* const* d_in, const int* in_sizes, int n_in,
                              void* d_out, int out_size) {
    const void* x = nullptr;
    const void* w = nullptr;
    const void* b = nullptr;
    for (int i = 0; i < n_in; i++) {
        if (in_sizes[i] == M_DIM * K_DIM)      x = d_in[i];
        else if (in_sizes[i] == K_DIM * N_DIM) w = d_in[i];
        else                                   b = d_in[i];
    }
    float* out = (float*)d_out;

    if (g_tma_ok < 0) {
        cudaFuncSetAttribute(tc_gemm_tma,
                             cudaFuncAttributeMaxDynamicSharedMemorySize, SMEM_TOTAL);
        cudaFuncSetAttribute(tc_gemm_ca,
                             cudaFuncAttributeMaxDynamicSharedMemorySize, SMEM_TOTAL);
        setup_tma();
    }

    detect_kernel<<<1, 256>>>((const uint8_t*)x, (const uint8_t*)w);
    pack_x_bf16_kernel<<<(M_DIM * (size_t)K_DIM) / (256 * 16), 256>>>(x);
    pack_w_bf16T_kernel<<<dim3(N_DIM / 32, K_DIM / 32), dim3(32, 8)>>>(w);
    if (g_tma_ok)
        tc_gemm_tma<<<dim3(N_DIM / TBN, M_DIM / TBM), 256, SMEM_TOTAL>>>(
            h_mapA, h_mapB, (const __half*)b, out);
    else
        tc_gemm_ca<<<dim3(N_DIM / TBN, M_DIM / TBM), 256, SMEM_TOTAL>>>(
            (const __half*)b, out);
}